// round 10
// baseline (speedup 1.0000x reference)
#include <cuda_runtime.h>
#include <cstdint>

#define B 4
#define L 2048
#define H 8
#define D 64
#define NT 38           // n_top
#define SK 38           // sample_k
#define NIDX (L*SK)     // 77824
#define CH 32           // cumsum chunks
#define CROWS (L/CH)    // 64 rows per chunk
#define KC 64           // attention key-chunk
#define NC (L/KC)       // 32 attention chunks
#define BH (B*H)

// ---------------- scratch (no allocations allowed) ----------------
__device__ int    g_idx[NIDX];          // index_sample, row-major (q, j)
__device__ float  g_M[BH*L];            // sparsity metric
__device__ int    g_top[BH*NT];         // selected queries per (b,h), SORTED by q
__device__ float  g_csum[BH*CH*D];      // per-chunk column sums
__device__ float  g_pl[BH*NT*NC];       // attention partial sum(exp)
__device__ float  g_pacc[BH*NT*NC*D];   // attention partial sum(exp*V)

// ---------------- threefry2x32-20 (jax partitionable path) ----------------
__device__ __forceinline__ uint32_t rotl32(uint32_t x, int r) {
    return (x << r) | (x >> (32 - r));
}

__device__ __forceinline__ void threefry2x32(uint32_t k0, uint32_t k1,
                                             uint32_t x0, uint32_t x1,
                                             uint32_t& o0, uint32_t& o1) {
    uint32_t ks2 = k0 ^ k1 ^ 0x1BD11BDAu;
    x0 += k0; x1 += k1;
#define TF_R(R) { x0 += x1; x1 = rotl32(x1, (R)); x1 ^= x0; }
    TF_R(13) TF_R(15) TF_R(26) TF_R(6)
    x0 += k1;  x1 += ks2 + 1u;
    TF_R(17) TF_R(29) TF_R(16) TF_R(24)
    x0 += ks2; x1 += k0 + 2u;
    TF_R(13) TF_R(15) TF_R(26) TF_R(6)
    x0 += k0;  x1 += k1 + 3u;
    TF_R(17) TF_R(29) TF_R(16) TF_R(24)
    x0 += k1;  x1 += ks2 + 4u;
    TF_R(13) TF_R(15) TF_R(26) TF_R(6)
    x0 += ks2; x1 += k0 + 5u;
#undef TF_R
    o0 = x0; o1 = x1;
}

__global__ void k_genidx() {
    int t = blockIdx.x * blockDim.x + threadIdx.x;
    if (t >= NIDX) return;
    uint32_t c0, c1;
    threefry2x32(0u, 42u, 0u, 1u, c0, c1);   // lower key (constant-folds)
    uint32_t o0, o1;
    threefry2x32(c0, c1, 0u, (uint32_t)t, o0, o1);
    g_idx[t] = (int)((o0 ^ o1) & (uint32_t)(L - 1));
}

// ---------------- fused launch 1: k_M blocks + csum_partial blocks ----------------
__global__ void k_fused_M_csum(const float* __restrict__ Q, const float* __restrict__ K,
                               const float* __restrict__ V) {
    int bx = blockIdx.x;
    int tid = threadIdx.x;
    if (bx < 8192) {
        int bh = bx >> 8;
        int b = bh >> 3, h = bh & 7;
        int w = tid >> 5, l = tid & 31;
        int q = (bx & 255) * 8 + w;
        int s = l >> 3, c = l & 7;

        const float4* qr = (const float4*)(Q + (((size_t)b * L + q) * H + h) * D);
        float4 qa = qr[2 * c], qb = qr[2 * c + 1];
        const float4* Kb = (const float4*)(K + (((size_t)b * L) * H + h) * D);

        float mx = -1e30f, sm = 0.f;
        const int* ip = &g_idx[q * SK];
        #pragma unroll 2
        for (int j0 = 0; j0 < 40; j0 += 4) {
            int j = j0 + s;
            int jc = min(j, SK - 1);
            int k = ip[jc];
            const float4* kr = Kb + (size_t)k * (H * D / 4) + 2 * c;
            float4 ka = kr[0], kb = kr[1];
            float p = ka.x * qa.x + ka.y * qa.y + ka.z * qa.z + ka.w * qa.w
                    + kb.x * qb.x + kb.y * qb.y + kb.z * qb.z + kb.w * qb.w;
            p += __shfl_xor_sync(0xffffffffu, p, 1);
            p += __shfl_xor_sync(0xffffffffu, p, 2);
            p += __shfl_xor_sync(0xffffffffu, p, 4);
            bool valid = (j < SK);
            mx = fmaxf(mx, valid ? p : -1e30f);
            sm += valid ? p : 0.f;
        }
        mx = fmaxf(mx, __shfl_xor_sync(0xffffffffu, mx, 8));
        sm += __shfl_xor_sync(0xffffffffu, sm, 8);
        mx = fmaxf(mx, __shfl_xor_sync(0xffffffffu, mx, 16));
        sm += __shfl_xor_sync(0xffffffffu, sm, 16);
        if (l == 0) g_M[bh * L + q] = mx - sm * (1.0f / (float)L);
    } else {
        int idx = bx - 8192;
        int bh = idx >> 5, chunk = idx & 31;
        int b = bh >> 3, h = bh & 7;
        int c = tid & 63, r0 = tid >> 6;
        float s = 0.f;
        for (int r = r0; r < CROWS; r += 4)
            s += V[(((size_t)b * L + chunk * CROWS + r) * H + h) * D + c];
        __shared__ float red[256];
        red[tid] = s;
        __syncthreads();
        if (tid < 64)
            g_csum[((size_t)bh * CH + chunk) * D + c] =
                red[tid] + red[tid + 64] + red[tid + 128] + red[tid + 192];
    }
}

// ---------------- fused launch 2: topk blocks + csum_scan blocks ----------------
__global__ void k_fused_topk_scan(const float* __restrict__ V, float* __restrict__ out) {
    int bx = blockIdx.x;
    int tid = threadIdx.x;
    if (bx < BH) {
        int bh = bx;
        __shared__ float vals[L];
        __shared__ float wv[8];
        __shared__ int   wi[8];
        __shared__ int   sel[NT];
        int w = tid >> 5, lane = tid & 31;
        for (int i = tid; i < L; i += 256) vals[i] = g_M[bh * L + i];
        __syncthreads();
        for (int t = 0; t < NT; t++) {
            float bv = -1e38f; int bi = L;
            #pragma unroll
            for (int rep = 0; rep < L / 256; rep++) {
                int i = tid + rep * 256;
                float v = vals[i];
                if (v > bv || (v == bv && i < bi)) { bv = v; bi = i; }
            }
            #pragma unroll
            for (int off = 16; off; off >>= 1) {
                float ov = __shfl_down_sync(0xffffffffu, bv, off);
                int   oi = __shfl_down_sync(0xffffffffu, bi, off);
                if (ov > bv || (ov == bv && oi < bi)) { bv = ov; bi = oi; }
            }
            if (lane == 0) { wv[w] = bv; wi[w] = bi; }
            __syncthreads();
            if (tid == 0) {
                float fv = wv[0]; int fi = wi[0];
                #pragma unroll
                for (int ww = 1; ww < 8; ww++)
                    if (wv[ww] > fv || (wv[ww] == fv && wi[ww] < fi)) { fv = wv[ww]; fi = wi[ww]; }
                sel[t] = fi;
                vals[fi] = -1e38f;
            }
            __syncthreads();
        }
        if (tid < NT) {
            int v = sel[tid];
            int r = 0;
            #pragma unroll
            for (int i = 0; i < NT; i++) r += (sel[i] < v);
            g_top[bh * NT + r] = v;
        }
    } else {
        int idx = bx - BH;
        int bh = idx >> 5, chunk = idx & 31;
        int b = bh >> 3, h = bh & 7;
        __shared__ float tile[CROWS * 64];
        __shared__ float gsum[4 * 64];
        __shared__ float sbase[64];
        int c = tid & 63, g = tid >> 6;   // 4 groups x 16 rows

        if (tid < 64) {
            float s = 0.f;
            for (int cc = 0; cc < chunk; cc++)
                s += g_csum[((size_t)bh * CH + cc) * D + tid];
            sbase[tid] = s;
        }
        int r0 = chunk * CROWS;
        for (int i = tid; i < CROWS * 64; i += 256) {
            int r = i >> 6, cc = i & 63;
            tile[i] = V[(((size_t)b * L + r0 + r) * H + h) * D + cc];
        }
        __syncthreads();

        float s = 0.f;
        int rb = g * 16;
        #pragma unroll
        for (int r = 0; r < 16; r++) {
            s += tile[(rb + r) * 64 + c];
            tile[(rb + r) * 64 + c] = s;
        }
        gsum[g * 64 + c] = s;
        __syncthreads();

        float prefix = sbase[c];
        for (int gg = 0; gg < g; gg++) prefix += gsum[gg * 64 + c];
        #pragma unroll
        for (int r = 0; r < 16; r++)
            out[(((size_t)b * L + r0 + rb + r) * H + h) * D + c] =
                tile[(rb + r) * 64 + c] + prefix;
    }
}

// ---------------- attention split-K: K-in-registers, shuffle-pipe broadcasts ----
// Block (bh, chunk): 64 keys. g_top sorted -> active suffix [lo, NT).
// Phase A: warp w owns keys w*8..w*8+7; lane = (key=lane>>2, dq=lane&3);
//   16 K floats per lane IN REGISTERS (one gmem load, reused for all queries).
//   Per query: 16 FMA + 2 shuffles + exp; Q from sQ (8-way broadcast dedup).
// Phase B: warp owns 5 queries; their 64 exp-scores live in 10 regs
//   (2 LDS/query); per-key e via __shfl_sync (shuffle pipe, 0 smem);
//   V float2 from smem conflict-free, shared across the 5 queries.
__global__ void __launch_bounds__(256)
k_attn_part(const float* __restrict__ Q, const float* __restrict__ K,
            const float* __restrict__ V) {
    int bh = blockIdx.x, chunk = blockIdx.y;
    int b = bh >> 3, h = bh & 7;
    int c0 = chunk * KC;
    int tid = threadIdx.x;
    int w = tid >> 5, lane = tid & 31;

    __shared__ float4 sV[KC * 16];
    __shared__ float4 sQ[NT * 16];
    __shared__ float  sE[NT][KC];
    __shared__ int    sTop[NT];
    __shared__ int    s_lo;

    if (tid < NT) sTop[tid] = g_top[bh * NT + tid];
    __syncthreads();
    if (tid == 0) {
        int lo = NT;
        for (int i = 0; i < NT; i++)
            if (sTop[i] >= c0) { lo = i; break; }
        s_lo = lo;
    }
    __syncthreads();
    int lo = s_lo;
    if (lo >= NT) return;   // no active queries in this chunk

    const float4* K4 = (const float4*)K;
    const float4* V4 = (const float4*)V;
    const float4* Q4 = (const float4*)Q;

    // stage V (natural layout) and active Q rows
    for (int i = tid; i < KC * 16; i += 256) {
        int row = i >> 4, f = i & 15;
        sV[i] = V4[((size_t)(b * L + c0 + row) * H + h) * 16 + f];
    }
    for (int i = tid; i < (NT - lo) * 16; i += 256) {
        int t = lo + (i >> 4), f = i & 15;
        sQ[t * 16 + f] = Q4[((size_t)(b * L + sTop[t]) * H + h) * 16 + f];
    }

    // K fragment to registers: key kk = w*8 + (lane>>2), dims [dq*16, dq*16+16)
    int kk = w * 8 + (lane >> 2);
    int dq = lane & 3;
    float4 kf0, kf1, kf2, kf3;
    {
        size_t koff = ((size_t)(b * L + c0 + kk) * H + h) * 16 + dq * 4;
        kf0 = K4[koff];  kf1 = K4[koff + 1];
        kf2 = K4[koff + 2]; kf3 = K4[koff + 3];
    }
    __syncthreads();

    const float scale = 0.125f;

    // ---- Phase A: all warps loop over all active queries ----
    for (int t = lo; t < NT; t++) {
        int q = sTop[t];
        int nk = min(KC, q - c0 + 1);
        const float4* qr = &sQ[t * 16 + dq * 4];
        float4 q0 = qr[0], q1 = qr[1], q2 = qr[2], q3 = qr[3];
        float d = kf0.x * q0.x + kf0.y * q0.y + kf0.z * q0.z + kf0.w * q0.w
                + kf1.x * q1.x + kf1.y * q1.y + kf1.z * q1.z + kf1.w * q1.w
                + kf2.x * q2.x + kf2.y * q2.y + kf2.z * q2.z + kf2.w * q2.w
                + kf3.x * q3.x + kf3.y * q3.y + kf3.z * q3.z + kf3.w * q3.w;
        d += __shfl_xor_sync(0xffffffffu, d, 1);
        d += __shfl_xor_sync(0xffffffffu, d, 2);
        float e = (kk < nk) ? __expf(d * scale) : 0.f;
        if (dq == 0) sE[t][kk] = e;
    }
    __syncthreads();

    // ---- Phase B: 5 queries per warp; e in regs, broadcast via shuffle ----
    const float2* sV2 = (const float2*)sV;
    float e0[5], e1[5];
    float acc[5][2];
    bool val[5];
    #pragma unroll
    for (int j = 0; j < 5; j++) {
        int t = lo + w + 8 * j;
        val[j] = (t < NT);
        int tc = val[j] ? t : lo;
        e0[j] = sE[tc][lane];
        e1[j] = sE[tc][lane + 32];
        acc[j][0] = 0.f; acc[j][1] = 0.f;
    }

    // lsum per query (warp reduce of e0+e1)
    #pragma unroll
    for (int j = 0; j < 5; j++) {
        float ls = e0[j] + e1[j];
        #pragma unroll
        for (int off = 16; off; off >>= 1)
            ls += __shfl_xor_sync(0xffffffffu, ls, off);
        if (val[j] && lane == 0)
            g_pl[(bh * NT + lo + w + 8 * j) * NC + chunk] = ls;
    }

    #pragma unroll 4
    for (int k = 0; k < KC; k++) {
        float2 v = sV2[k * 32 + lane];
        int src = k & 31;
        if (k < 32) {
            #pragma unroll
            for (int j = 0; j < 5; j++) {
                float e = __shfl_sync(0xffffffffu, e0[j], src);
                acc[j][0] += e * v.x;
                acc[j][1] += e * v.y;
            }
        } else {
            #pragma unroll
            for (int j = 0; j < 5; j++) {
                float e = __shfl_sync(0xffffffffu, e1[j], src);
                acc[j][0] += e * v.x;
                acc[j][1] += e * v.y;
            }
        }
    }
    #pragma unroll
    for (int j = 0; j < 5; j++) {
        if (val[j]) {
            int t = lo + w + 8 * j;
            float2* pa = (float2*)&g_pacc[((size_t)(bh * NT + t) * NC + chunk) * D];
            pa[lane] = make_float2(acc[j][0], acc[j][1]);
        }
    }
}

// ---------------- attention merge: only chunks ch <= q/KC were written ----------------
__global__ void k_attn_merge(float* __restrict__ out) {
    int u = blockIdx.x;                 // (bh, sidx)
    int bh = u / NT, sidx = u % NT;
    int b = bh >> 3, h = bh & 7;
    int q = g_top[bh * NT + sidx];
    int d = threadIdx.x;                // 64 threads
    int nch = (q >> 6) + 1;

    float den = 0.f, num = 0.f;
    for (int ch = 0; ch < nch; ch++) {
        den += g_pl[u * NC + ch];
        num += g_pacc[((size_t)u * NC + ch) * D + d];
    }
    out[(((size_t)b * L + q) * H + h) * D + d] = num / den;
}

// ---------------- launch ----------------
extern "C" void kernel_launch(void* const* d_in, const int* in_sizes, int n_in,
                              void* d_out, int out_size) {
    (void)in_sizes; (void)n_in; (void)out_size;
    const float* Q = (const float*)d_in[0];
    const float* K = (const float*)d_in[1];
    const float* V = (const float*)d_in[2];
    float* out = (float*)d_out;

    k_genidx<<<(NIDX + 255) / 256, 256>>>();
    k_fused_M_csum<<<8192 + 1024, 256>>>(Q, K, V);
    k_fused_topk_scan<<<BH + 1024, 256>>>(V, out);
    k_attn_part<<<dim3(BH, NC), 256>>>(Q, K, V);   // profile slot #4
    k_attn_merge<<<BH * NT, 64>>>(out);
}